// round 14
// baseline (speedup 1.0000x reference)
#include <cuda_runtime.h>
#include <cuda_bf16.h>
#include <cstdint>

// ---------------------------------------------------------------------------
// Problem constants
// ---------------------------------------------------------------------------
#define BB     8
#define NN     256
#define FD     1024
#define HH     256
#define M_ROWS (BB * NN)          // 2048
#define KSEL   39321              // int(0.6 * 256 * 256)
#define QSZ    (BB * NN * NN)     // 524288 per output tensor

// Scratch (device globals — no allocation allowed)
__device__ float g_pr[M_ROWS * HH];   // pr + b1
__device__ float g_pc[M_ROWS * HH];

// Monotone float<->uint key (total order incl. negatives)
__device__ __forceinline__ unsigned fkey(float x) {
    unsigned u = __float_as_uint(x);
    return (u & 0x80000000u) ? ~u : (u | 0x80000000u);
}
__device__ __forceinline__ float funkey(unsigned k) {
    return (k & 0x80000000u) ? __uint_as_float(k ^ 0x80000000u)
                             : __uint_as_float(~k);
}

__device__ __forceinline__ uint32_t smem_u32(const void* p) {
    uint32_t a;
    asm("{ .reg .u64 t; cvta.to.shared.u64 t, %1; cvt.u32.u64 %0, t; }"
        : "=r"(a) : "l"(p));
    return a;
}
__device__ __forceinline__ uint32_t swz128(uint32_t off) {
    return off ^ ((off >> 3) & 0x70u);
}
__device__ __forceinline__ void cpa16(uint32_t saddr, const void* g) {
    asm volatile("cp.async.cg.shared.global [%0], [%1], 16;"
                 :: "r"(saddr), "l"(g));
}
__device__ __forceinline__ void ldsm4(uint32_t* r, uint32_t addr) {
    asm volatile("ldmatrix.sync.aligned.m8n8.x4.shared.b16 {%0,%1,%2,%3}, [%4];"
                 : "=r"(r[0]), "=r"(r[1]), "=r"(r[2]), "=r"(r[3]) : "r"(addr));
}
// tf32 mma m16n8k8
__device__ __forceinline__ void mma_tf32(float* d, const uint32_t* a,
                                         const uint32_t* b) {
    asm volatile("mma.sync.aligned.m16n8k8.row.col.f32.tf32.tf32.f32 "
        "{%0,%1,%2,%3}, {%4,%5,%6,%7}, {%8,%9}, {%0,%1,%2,%3};"
        : "+f"(d[0]), "+f"(d[1]), "+f"(d[2]), "+f"(d[3])
        : "r"(a[0]), "r"(a[1]), "r"(a[2]), "r"(a[3]), "r"(b[0]), "r"(b[1]));
}
// in-register tf32 hi/lo split
__device__ __forceinline__ void split1(uint32_t v, uint32_t& h, uint32_t& l) {
    float f = __uint_as_float(v);
    uint32_t hu;
    asm("cvt.rna.tf32.f32 %0, %1;" : "=r"(hu) : "f"(f));
    h = hu;
    l = __float_as_uint(f - __uint_as_float(hu));
}
__device__ __forceinline__ void split4(const uint32_t* v, uint32_t* h,
                                       uint32_t* l) {
#pragma unroll
    for (int i = 0; i < 4; i++) split1(v[i], h[i], l[i]);
}

// ---------------------------------------------------------------------------
// Kernel 1: 3-term split-TF32 GEMM, 3-stage cp.async, fragment double-buffer
//   C[2048, 512] = X · Wcat^T ; CTA tile 128x64, kc=32.
// ---------------------------------------------------------------------------
#define STAGE_SZ  24576
#define GEMM_SMEM (3 * STAGE_SZ)

__global__ __launch_bounds__(256, 1) void gemm_mma_kernel(
        const float* __restrict__ x,
        const float* __restrict__ W1,
        const float* __restrict__ b1) {
    extern __shared__ char smem[];
    const uint32_t sb = smem_u32(smem);
    const int tid = threadIdx.x;
    const int lane = tid & 31;
    const int wid = tid >> 5;
    const int wm = wid & 3;            // m warp: 0..3 (32 rows each)
    const int wn = wid >> 2;           // n warp: 0..1 (32 cols each)
    const int bm = blockIdx.y * 128;
    const int bn = blockIdx.x * 64;
    const int sel = (bn >= 256) ? 1 : 0;

    // ---- cp.async maps ----
    uint32_t sswA[4]; long gA[4];
#pragma unroll
    for (int i = 0; i < 4; i++) {
        int idx = tid + i * 256;
        int row = idx >> 3, cb = idx & 7;
        sswA[i] = swz128((uint32_t)(row * 128 + cb * 16));
        gA[i] = (long)(bm + row) * 1024 + cb * 4;
    }
    uint32_t sswB[2]; long gB[2];
#pragma unroll
    for (int i = 0; i < 2; i++) {
        int idx = tid + i * 256;
        int row = idx >> 3, cb = idx & 7;
        sswB[i] = swz128((uint32_t)(row * 128 + cb * 16));
        gB[i] = (long)(bn - sel * 256 + row) * 2048 + sel * 1024 + cb * 4;
    }

#define LOAD_CHUNK(stage, ch) do {                                            \
    uint32_t so_ = sb + (stage) * STAGE_SZ;                                   \
    _Pragma("unroll")                                                         \
    for (int i = 0; i < 4; i++)                                               \
        cpa16(so_ + sswA[i], x + gA[i] + (ch) * 32);                          \
    _Pragma("unroll")                                                         \
    for (int i = 0; i < 2; i++)                                               \
        cpa16(so_ + 16384 + sswB[i], W1 + gB[i] + (ch) * 32);                 \
    asm volatile("cp.async.commit_group;" ::: "memory");                      \
} while (0)

    // ---- ldmatrix lane addressing (fp32, 128B rows, SW128) ----
    const int ag = lane >> 3;
    const int aRow = wm * 32 + (ag & 1) * 8 + (lane & 7);
    const int aG2 = ag >> 1;
    const uint32_t ax = (uint32_t)(lane & 7) << 4;
    uint32_t aRB[2];
#pragma unroll
    for (int mt = 0; mt < 2; mt++) aRB[mt] = (uint32_t)(aRow + mt * 16) * 128;

    const int bNtl = (lane >> 4) & 1;
    const int bCb = (lane >> 3) & 1;
    uint32_t bRB[2];
#pragma unroll
    for (int p = 0; p < 2; p++) {
        int n = wn * 32 + p * 16 + bNtl * 8 + (lane & 7);
        bRB[p] = (uint32_t)n * 128;
    }

    float acc[2][4][4];
#pragma unroll
    for (int mt = 0; mt < 2; mt++)
#pragma unroll
        for (int nt = 0; nt < 4; nt++)
#pragma unroll
            for (int r = 0; r < 4; r++) acc[mt][nt][r] = 0.f;

    uint32_t aF[2][2][4], bF[2][2][4];
    uint32_t aH[2][2][4], aL[2][2][4], bH[2][2][4], bL[2][2][4];

#define LDFRAGS(buf, st_, j) do {                                             \
    const uint32_t aCol_ = (uint32_t)((((j) * 2 + aG2) << 4)) ^ ax;           \
    const uint32_t bCol_ = (uint32_t)((((j) * 2 + bCb) << 4)) ^ ax;           \
    ldsm4(aF[buf][0], (st_) + aRB[0] + aCol_);                                \
    ldsm4(aF[buf][1], (st_) + aRB[1] + aCol_);                                \
    ldsm4(bF[buf][0], (st_) + 16384 + bRB[0] + bCol_);                        \
    ldsm4(bF[buf][1], (st_) + 16384 + bRB[1] + bCol_);                        \
} while (0)

#define SPLITFRAGS(buf) do {                                                  \
    split4(aF[buf][0], aH[buf][0], aL[buf][0]);                               \
    split4(aF[buf][1], aH[buf][1], aL[buf][1]);                               \
    split4(bF[buf][0], bH[buf][0], bL[buf][0]);                               \
    split4(bF[buf][1], bH[buf][1], bL[buf][1]);                               \
} while (0)

#define MMAS(buf) do {                                                        \
    _Pragma("unroll")                                                         \
    for (int mt = 0; mt < 2; mt++)                                            \
        _Pragma("unroll")                                                     \
        for (int nt = 0; nt < 4; nt++) {                                      \
            const int p_ = nt >> 1, s_ = (nt & 1) * 2;                        \
            mma_tf32(acc[mt][nt], aH[buf][mt], &bH[buf][p_][s_]);             \
            mma_tf32(acc[mt][nt], aH[buf][mt], &bL[buf][p_][s_]);             \
            mma_tf32(acc[mt][nt], aL[buf][mt], &bH[buf][p_][s_]);             \
        }                                                                     \
} while (0)

    LOAD_CHUNK(0, 0);
    LOAD_CHUNK(1, 1);

    int sidx = 0;
    for (int ch = 0; ch < 32; ch++) {
        if (ch < 31)
            asm volatile("cp.async.wait_group 1;" ::: "memory");
        else
            asm volatile("cp.async.wait_group 0;" ::: "memory");
        __syncthreads();
        if (ch < 30) {
            int ns = sidx + 2; if (ns >= 3) ns -= 3;
            LOAD_CHUNK(ns, ch + 2);
        }

        const uint32_t st = sb + sidx * STAGE_SZ;
        LDFRAGS(0, st, 0);
        SPLITFRAGS(0);
#pragma unroll
        for (int j = 0; j < 4; j++) {
            const int cb2 = j & 1, nb = cb2 ^ 1;
            if (j < 3) LDFRAGS(nb, st, j + 1);
            MMAS(cb2);
            if (j < 3) SPLITFRAGS(nb);
        }
        sidx++; if (sidx == 3) sidx = 0;
    }

    // ---- epilogue ----
    const int mBase = bm + wm * 32 + (lane >> 2);
    const int nBase = bn + wn * 32 + (lane & 3) * 2;
#pragma unroll
    for (int mt = 0; mt < 2; mt++) {
#pragma unroll
        for (int nt = 0; nt < 4; nt++) {
            int m = mBase + mt * 16;
            int n = nBase + nt * 8;
            float d0 = acc[mt][nt][0], d1 = acc[mt][nt][1];
            float d2 = acc[mt][nt][2], d3 = acc[mt][nt][3];
            if (n < 256) {
                float bv0 = b1[n], bv1 = b1[n + 1];
                *(float2*)&g_pr[m * 256 + n] = make_float2(d0 + bv0, d1 + bv1);
                *(float2*)&g_pr[(m + 8) * 256 + n] = make_float2(d2 + bv0, d3 + bv1);
            } else {
                int nc = n - 256;
                *(float2*)&g_pc[m * 256 + nc] = make_float2(d0, d1);
                *(float2*)&g_pc[(m + 8) * 256 + nc] = make_float2(d2, d3);
            }
        }
    }
#undef LOAD_CHUNK
#undef LDFRAGS
#undef SPLITFRAGS
#undef MMAS
}

// ---------------------------------------------------------------------------
// Kernel 2: edge scores.  Tile 32(i) x 64(j), h in two 128-halves.
// ---------------------------------------------------------------------------
#define EDGE_SMEM (16384 + 32768 + 512)

__global__ __launch_bounds__(256) void edge_kernel(const float* __restrict__ W2,
                                                   const float* __restrict__ b2,
                                                   float* __restrict__ out_edge) {
    extern __shared__ float se[];
    float* spr = se;             // [128][32] h-major
    float* spc = se + 4096;      // [128][64]
    float* sw2 = se + 12288;     // [128]

    const int tid = threadIdx.x;
    const int b  = blockIdx.z;
    const int i0 = blockIdx.y * 32;
    const int j0 = blockIdx.x * 64;
    const int tx = tid & 15;     // j: 4 each
    const int ty = tid >> 4;     // i: 2 each

    float acc[2][4];
#pragma unroll
    for (int r = 0; r < 2; r++)
#pragma unroll
        for (int c = 0; c < 4; c++) acc[r][c] = 0.f;

    const float4* pr4 = (const float4*)g_pr;
    const float4* pc4 = (const float4*)g_pc;

#pragma unroll
    for (int hh = 0; hh < 2; hh++) {
        if (hh) __syncthreads();

#pragma unroll
        for (int u = 0; u < 4; u++) {
            int t = tid + u * 256;
            int i = t & 31, hq = t >> 5;
            float4 v = pr4[(b * 256 + i0 + i) * 64 + hh * 32 + hq];
            spr[(hq * 4 + 0) * 32 + i] = v.x;
            spr[(hq * 4 + 1) * 32 + i] = v.y;
            spr[(hq * 4 + 2) * 32 + i] = v.z;
            spr[(hq * 4 + 3) * 32 + i] = v.w;
        }
#pragma unroll
        for (int u = 0; u < 8; u++) {
            int t = tid + u * 256;
            int j = t & 63, hq = t >> 6;
            float4 v = pc4[(b * 256 + j0 + j) * 64 + hh * 32 + hq];
            spc[(hq * 4 + 0) * 64 + j] = v.x;
            spc[(hq * 4 + 1) * 64 + j] = v.y;
            spc[(hq * 4 + 2) * 64 + j] = v.z;
            spc[(hq * 4 + 3) * 64 + j] = v.w;
        }
        if (tid < 128) sw2[tid] = W2[hh * 128 + tid];
        __syncthreads();

#pragma unroll 2
        for (int h = 0; h < 128; h++) {
            float2 a = *(const float2*)&spr[h * 32 + ty * 2];
            float4 c = *(const float4*)&spc[h * 64 + tx * 4];
            float w = sw2[h];
            float av[2] = {a.x, a.y};
            float cv[4] = {c.x, c.y, c.z, c.w};
#pragma unroll
            for (int r = 0; r < 2; r++)
#pragma unroll
                for (int cc = 0; cc < 4; cc++) {
                    float t = av[r] + cv[cc];
                    t = fmaxf(t, 0.f);
                    acc[r][cc] = fmaf(t, w, acc[r][cc]);
                }
        }
    }

    const float bbv = b2[0];
#pragma unroll
    for (int r = 0; r < 2; r++) {
        float4 o;
        o.x = acc[r][0] + bbv;
        o.y = acc[r][1] + bbv;
        o.z = acc[r][2] + bbv;
        o.w = acc[r][3] + bbv;
        *(float4*)&out_edge[b * 65536 + (i0 + ty * 2 + r) * 256 + j0 + tx * 4] = o;
    }
}

// ---------------------------------------------------------------------------
// Kernel 3: fused select + finalize.  One CTA per batch (grid 8 x 1024).
//   3-pass radix select (10/11/11 bits) on edge fkeys + max + S/T, then
//   write soft / causal / conf for the whole batch.
// ---------------------------------------------------------------------------
__global__ __launch_bounds__(1024) void select_finalize_kernel(
        const float* __restrict__ edge,
        float* __restrict__ causal,
        float* __restrict__ conf,
        float* __restrict__ soft) {
    __shared__ unsigned int hist[2048];
    __shared__ unsigned int csum[32];
    __shared__ unsigned int s_prefix;
    __shared__ int s_r;
    __shared__ unsigned int redM[32];
    __shared__ float redS[32], redT[32];
    __shared__ float sh_M, sh_invS, sh_invC;
    __shared__ unsigned sh_thr;

    const int b = blockIdx.x, tid = threadIdx.x;
    const int lane = tid & 31;
    const float4* v4 = (const float4*)(edge + b * 65536);

    if (tid == 0) { s_prefix = 0u; s_r = KSEL; }

    unsigned umax = 0u;
#pragma unroll
    for (int pass = 0; pass < 3; pass++) {
        hist[tid] = 0u; hist[tid + 1024] = 0u;
        __syncthreads();
        const unsigned int pref = s_prefix;
        const int shift = (pass == 0) ? 22 : (pass == 1 ? 11 : 0);
        const int hishift = (pass == 1) ? 22 : 11;

        for (int it = tid; it < 16384; it += 1024) {
            float4 q = v4[it];
            float ff[4] = {q.x, q.y, q.z, q.w};
#pragma unroll
            for (int c = 0; c < 4; c++) {
                unsigned int u = fkey(ff[c]);
                if (pass == 0) umax = umax > u ? umax : u;
                bool ok = (pass == 0) || ((u >> hishift) == pref);
                int bin = (int)((u >> shift) & 2047u);
                unsigned int peers = __match_any_sync(0xffffffffu, ok ? bin : -1);
                if (ok && lane == (__ffs(peers) - 1))
                    atomicAdd(&hist[bin], (unsigned)__popc(peers));
            }
        }
        if (pass == 0) {
            unsigned m = umax;
            for (int o = 16; o > 0; o >>= 1)
                m = max(m, __shfl_down_sync(0xffffffffu, m, o));
            if (lane == 0) redM[tid >> 5] = m;
        }
        __syncthreads();

        if (tid < 32) {
            unsigned s = 0;
#pragma unroll 8
            for (int k = 0; k < 64; k++) s += hist[tid * 64 + k];
            csum[tid] = s;
        }
        __syncthreads();
        if (tid == 0) {
            int r = s_r; unsigned cum = 0; int chunk = 0;
            for (int ci = 31; ci >= 0; ci--) {
                if (cum + csum[ci] >= (unsigned)r) { chunk = ci; break; }
                cum += csum[ci];
            }
            int binf = 0;
            for (int k = 63; k >= 0; k--) {
                unsigned c = hist[chunk * 64 + k];
                if (cum + c >= (unsigned)r) { binf = chunk * 64 + k; break; }
                cum += c;
            }
            s_prefix = (pass == 0) ? (unsigned)binf
                                   : ((s_prefix << 11) | (unsigned)binf);
            s_r = r - (int)cum;
            if (pass == 0) {
                unsigned m = 0;
                for (int w = 0; w < 32; w++) m = max(m, redM[w]);
                sh_M = funkey(m);
            }
        }
        __syncthreads();
    }

    const unsigned thrkey = s_prefix;
    const float M = sh_M;
    float S = 0.f, T = 0.f;
    for (int it = tid; it < 16384; it += 1024) {
        float4 q = v4[it];
        float ff[4] = {q.x, q.y, q.z, q.w};
#pragma unroll
        for (int c = 0; c < 4; c++) {
            float p = expf(2.f * (ff[c] - M));
            S += p;
            if (fkey(ff[c]) >= thrkey) T += p;
        }
    }
    for (int o = 16; o > 0; o >>= 1) {
        S += __shfl_down_sync(0xffffffffu, S, o);
        T += __shfl_down_sync(0xffffffffu, T, o);
    }
    if (lane == 0) { redS[tid >> 5] = S; redT[tid >> 5] = T; }
    __syncthreads();
    if (tid == 0) {
        float s = 0.f, t = 0.f;
#pragma unroll
        for (int w = 0; w < 32; w++) { s += redS[w]; t += redT[w]; }
        sh_invS = 1.f / s;
        sh_invC = 1.f / (t + 1e-12f * s);
        sh_thr = thrkey;
    }
    __syncthreads();

    // ---- finalize this batch ----
    const float invS = sh_invS, invC = sh_invC;
    const unsigned tk = sh_thr;
    float4* so4 = (float4*)(soft + b * 65536);
    float4* ca4 = (float4*)(causal + b * 65536);
    float4* cf4 = (float4*)(conf + b * 65536);
    for (int it = tid; it < 16384; it += 1024) {
        float4 q = v4[it];
        float ff[4] = {q.x, q.y, q.z, q.w};
        float4 so, ca, cf;
        float* sop = &so.x; float* cap = &ca.x; float* cfp = &cf.x;
#pragma unroll
        for (int c = 0; c < 4; c++) {
            float p = expf(2.f * (ff[c] - M));
            sop[c] = p * invS;
            float cc = (fkey(ff[c]) >= tk) ? p * invC : 0.f;
            cap[c] = cc;
            cfp[c] = 1.f - cc;
        }
        so4[it] = so;
        ca4[it] = ca;
        cf4[it] = cf;
    }
}

// ---------------------------------------------------------------------------
// Launch — 3 kernels
// ---------------------------------------------------------------------------
extern "C" void kernel_launch(void* const* d_in, const int* in_sizes, int n_in,
                              void* d_out, int out_size) {
    const float* x  = (const float*)d_in[0];
    const float* W1 = (const float*)d_in[1];
    const float* b1 = (const float*)d_in[2];
    const float* W2 = (const float*)d_in[3];
    const float* b2 = (const float*)d_in[4];

    float* out = (float*)d_out;
    float* o_causal = out;
    float* o_conf   = out + QSZ;
    float* o_edge   = out + 2 * QSZ;
    float* o_soft   = out + 3 * QSZ;

    cudaFuncSetAttribute(gemm_mma_kernel,
                         cudaFuncAttributeMaxDynamicSharedMemorySize, GEMM_SMEM);
    cudaFuncSetAttribute(edge_kernel,
                         cudaFuncAttributeMaxDynamicSharedMemorySize, EDGE_SMEM);

    gemm_mma_kernel<<<dim3(8, 16), 256, GEMM_SMEM>>>(x, W1, b1);
    edge_kernel<<<dim3(4, 8, BB), 256, EDGE_SMEM>>>(W2, b2, o_edge);
    select_finalize_kernel<<<BB, 1024>>>(o_edge, o_causal, o_conf, o_soft);
}

// round 15
// speedup vs baseline: 1.0667x; 1.0667x over previous
#include <cuda_runtime.h>
#include <cuda_bf16.h>
#include <cstdint>

// ---------------------------------------------------------------------------
// Problem constants
// ---------------------------------------------------------------------------
#define BB     8
#define NN     256
#define FD     1024
#define HH     256
#define M_ROWS (BB * NN)          // 2048
#define KSEL   39321              // int(0.6 * 256 * 256)
#define QSZ    (BB * NN * NN)     // 524288 per output tensor

// Scratch (device globals — no allocation allowed)
__device__ float g_pr[M_ROWS * HH];   // pr + b1
__device__ float g_pc[M_ROWS * HH];
__device__ unsigned g_maxkey[BB];
__device__ unsigned g_thrkey[BB];
__device__ float g_S[BB];
__device__ float g_T[BB];

// Monotone float<->uint key (total order incl. negatives)
__device__ __forceinline__ unsigned fkey(float x) {
    unsigned u = __float_as_uint(x);
    return (u & 0x80000000u) ? ~u : (u | 0x80000000u);
}
__device__ __forceinline__ float funkey(unsigned k) {
    return (k & 0x80000000u) ? __uint_as_float(k ^ 0x80000000u)
                             : __uint_as_float(~k);
}

__device__ __forceinline__ uint32_t smem_u32(const void* p) {
    uint32_t a;
    asm("{ .reg .u64 t; cvta.to.shared.u64 t, %1; cvt.u32.u64 %0, t; }"
        : "=r"(a) : "l"(p));
    return a;
}
__device__ __forceinline__ uint32_t swz128(uint32_t off) {
    return off ^ ((off >> 3) & 0x70u);
}
__device__ __forceinline__ void cpa16(uint32_t saddr, const void* g) {
    asm volatile("cp.async.cg.shared.global [%0], [%1], 16;"
                 :: "r"(saddr), "l"(g));
}
__device__ __forceinline__ void ldsm4(uint32_t* r, uint32_t addr) {
    asm volatile("ldmatrix.sync.aligned.m8n8.x4.shared.b16 {%0,%1,%2,%3}, [%4];"
                 : "=r"(r[0]), "=r"(r[1]), "=r"(r[2]), "=r"(r[3]) : "r"(addr));
}
// tf32 mma m16n8k8
__device__ __forceinline__ void mma_tf32(float* d, const uint32_t* a,
                                         const uint32_t* b) {
    asm volatile("mma.sync.aligned.m16n8k8.row.col.f32.tf32.tf32.f32 "
        "{%0,%1,%2,%3}, {%4,%5,%6,%7}, {%8,%9}, {%0,%1,%2,%3};"
        : "+f"(d[0]), "+f"(d[1]), "+f"(d[2]), "+f"(d[3])
        : "r"(a[0]), "r"(a[1]), "r"(a[2]), "r"(a[3]), "r"(b[0]), "r"(b[1]));
}
// in-register tf32 hi/lo split
__device__ __forceinline__ void split1(uint32_t v, uint32_t& h, uint32_t& l) {
    float f = __uint_as_float(v);
    uint32_t hu;
    asm("cvt.rna.tf32.f32 %0, %1;" : "=r"(hu) : "f"(f));
    h = hu;
    l = __float_as_uint(f - __uint_as_float(hu));
}
__device__ __forceinline__ void split4(const uint32_t* v, uint32_t* h,
                                       uint32_t* l) {
#pragma unroll
    for (int i = 0; i < 4; i++) split1(v[i], h[i], l[i]);
}

// ---------------------------------------------------------------------------
// Kernel 1: 3-term split-TF32 GEMM.  CTA tile 64x64 (grid 256 -> ~2 CTAs/SM),
//   kc=32, 3-stage cp.async (16KB/stage), fragment double-buffer.
// ---------------------------------------------------------------------------
#define STAGE_SZ  16384
#define GEMM_SMEM (3 * STAGE_SZ)

__global__ __launch_bounds__(256) void gemm_mma_kernel(
        const float* __restrict__ x,
        const float* __restrict__ W1,
        const float* __restrict__ b1) {
    extern __shared__ char smem[];
    const uint32_t sb = smem_u32(smem);
    const int tid = threadIdx.x;
    const int lane = tid & 31;
    const int wid = tid >> 5;
    const int wm = wid & 3;            // m warp: 0..3 (16 rows each)
    const int wn = wid >> 2;           // n warp: 0..1 (32 cols each)
    const int bm = blockIdx.y * 64;
    const int bn = blockIdx.x * 64;
    const int sel = (bn >= 256) ? 1 : 0;

    // ---- cp.async maps (A: 512 chunks, B: 512 chunks; 2 each per thread) ----
    uint32_t sswA[2]; long gA[2];
    uint32_t sswB[2]; long gB[2];
#pragma unroll
    for (int i = 0; i < 2; i++) {
        int idx = tid + i * 256;
        int row = idx >> 3, cb = idx & 7;
        uint32_t sw = swz128((uint32_t)(row * 128 + cb * 16));
        sswA[i] = sw;
        sswB[i] = sw;
        gA[i] = (long)(bm + row) * 1024 + cb * 4;
        gB[i] = (long)(bn - sel * 256 + row) * 2048 + sel * 1024 + cb * 4;
    }

#define LOAD_CHUNK(stage, ch) do {                                            \
    uint32_t so_ = sb + (stage) * STAGE_SZ;                                   \
    _Pragma("unroll")                                                         \
    for (int i = 0; i < 2; i++) {                                             \
        cpa16(so_ + sswA[i], x + gA[i] + (ch) * 32);                          \
        cpa16(so_ + 8192 + sswB[i], W1 + gB[i] + (ch) * 32);                  \
    }                                                                         \
    asm volatile("cp.async.commit_group;" ::: "memory");                      \
} while (0)

    // ---- ldmatrix lane addressing (fp32, 128B rows, SW128) ----
    const int ag = lane >> 3;
    const uint32_t aRB = (uint32_t)(wm * 16 + (ag & 1) * 8 + (lane & 7)) * 128;
    const int aG2 = ag >> 1;
    const uint32_t ax = (uint32_t)(lane & 7) << 4;

    const int bNtl = (lane >> 4) & 1;
    const int bCb = (lane >> 3) & 1;
    uint32_t bRB[2];
#pragma unroll
    for (int p = 0; p < 2; p++) {
        int n = wn * 32 + p * 16 + bNtl * 8 + (lane & 7);
        bRB[p] = (uint32_t)n * 128;
    }

    float acc[4][4];
#pragma unroll
    for (int nt = 0; nt < 4; nt++)
#pragma unroll
        for (int r = 0; r < 4; r++) acc[nt][r] = 0.f;

    uint32_t aF[2][4], bF[2][2][4];
    uint32_t aH[2][4], aL[2][4], bH[2][2][4], bL[2][2][4];

#define LDFRAGS(buf, st_, j) do {                                             \
    const uint32_t aCol_ = (uint32_t)((((j) * 2 + aG2) << 4)) ^ ax;           \
    const uint32_t bCol_ = (uint32_t)((((j) * 2 + bCb) << 4)) ^ ax;           \
    ldsm4(aF[buf], (st_) + aRB + aCol_);                                      \
    ldsm4(bF[buf][0], (st_) + 8192 + bRB[0] + bCol_);                         \
    ldsm4(bF[buf][1], (st_) + 8192 + bRB[1] + bCol_);                         \
} while (0)

#define SPLITFRAGS(buf) do {                                                  \
    split4(aF[buf], aH[buf], aL[buf]);                                        \
    split4(bF[buf][0], bH[buf][0], bL[buf][0]);                               \
    split4(bF[buf][1], bH[buf][1], bL[buf][1]);                               \
} while (0)

#define MMAS(buf) do {                                                        \
    _Pragma("unroll")                                                         \
    for (int nt = 0; nt < 4; nt++) {                                          \
        const int p_ = nt >> 1, s_ = (nt & 1) * 2;                            \
        mma_tf32(acc[nt], aH[buf], &bH[buf][p_][s_]);                         \
        mma_tf32(acc[nt], aH[buf], &bL[buf][p_][s_]);                         \
        mma_tf32(acc[nt], aL[buf], &bH[buf][p_][s_]);                         \
    }                                                                         \
} while (0)

    LOAD_CHUNK(0, 0);
    LOAD_CHUNK(1, 1);

    int sidx = 0;
    for (int ch = 0; ch < 32; ch++) {
        if (ch < 31)
            asm volatile("cp.async.wait_group 1;" ::: "memory");
        else
            asm volatile("cp.async.wait_group 0;" ::: "memory");
        __syncthreads();
        if (ch < 30) {
            int ns = sidx + 2; if (ns >= 3) ns -= 3;
            LOAD_CHUNK(ns, ch + 2);
        }

        const uint32_t st = sb + sidx * STAGE_SZ;
        LDFRAGS(0, st, 0);
        SPLITFRAGS(0);
#pragma unroll
        for (int j = 0; j < 4; j++) {
            const int cb2 = j & 1, nb = cb2 ^ 1;
            if (j < 3) LDFRAGS(nb, st, j + 1);
            MMAS(cb2);
            if (j < 3) SPLITFRAGS(nb);
        }
        sidx++; if (sidx == 3) sidx = 0;
    }

    // ---- epilogue ----
    const int mBase = bm + wm * 16 + (lane >> 2);
    const int nBase = bn + wn * 32 + (lane & 3) * 2;
#pragma unroll
    for (int nt = 0; nt < 4; nt++) {
        int n = nBase + nt * 8;
        float d0 = acc[nt][0], d1 = acc[nt][1];
        float d2 = acc[nt][2], d3 = acc[nt][3];
        if (n < 256) {
            float bv0 = b1[n], bv1 = b1[n + 1];
            *(float2*)&g_pr[mBase * 256 + n] = make_float2(d0 + bv0, d1 + bv1);
            *(float2*)&g_pr[(mBase + 8) * 256 + n] = make_float2(d2 + bv0, d3 + bv1);
        } else {
            int nc = n - 256;
            *(float2*)&g_pc[mBase * 256 + nc] = make_float2(d0, d1);
            *(float2*)&g_pc[(mBase + 8) * 256 + nc] = make_float2(d2, d3);
        }
    }
#undef LOAD_CHUNK
#undef LDFRAGS
#undef SPLITFRAGS
#undef MMAS
}

// ---------------------------------------------------------------------------
// Kernel 2: edge scores.  Tile 32(i) x 64(j), h in two 128-halves.
// ---------------------------------------------------------------------------
#define EDGE_SMEM (16384 + 32768 + 512)

__global__ __launch_bounds__(256) void edge_kernel(const float* __restrict__ W2,
                                                   const float* __restrict__ b2,
                                                   float* __restrict__ out_edge) {
    extern __shared__ float se[];
    float* spr = se;             // [128][32] h-major
    float* spc = se + 4096;      // [128][64]
    float* sw2 = se + 12288;     // [128]

    const int tid = threadIdx.x;
    const int b  = blockIdx.z;
    const int i0 = blockIdx.y * 32;
    const int j0 = blockIdx.x * 64;
    const int tx = tid & 15;     // j: 4 each
    const int ty = tid >> 4;     // i: 2 each

    float acc[2][4];
#pragma unroll
    for (int r = 0; r < 2; r++)
#pragma unroll
        for (int c = 0; c < 4; c++) acc[r][c] = 0.f;

    const float4* pr4 = (const float4*)g_pr;
    const float4* pc4 = (const float4*)g_pc;

#pragma unroll
    for (int hh = 0; hh < 2; hh++) {
        if (hh) __syncthreads();

#pragma unroll
        for (int u = 0; u < 4; u++) {
            int t = tid + u * 256;
            int i = t & 31, hq = t >> 5;
            float4 v = pr4[(b * 256 + i0 + i) * 64 + hh * 32 + hq];
            spr[(hq * 4 + 0) * 32 + i] = v.x;
            spr[(hq * 4 + 1) * 32 + i] = v.y;
            spr[(hq * 4 + 2) * 32 + i] = v.z;
            spr[(hq * 4 + 3) * 32 + i] = v.w;
        }
#pragma unroll
        for (int u = 0; u < 8; u++) {
            int t = tid + u * 256;
            int j = t & 63, hq = t >> 6;
            float4 v = pc4[(b * 256 + j0 + j) * 64 + hh * 32 + hq];
            spc[(hq * 4 + 0) * 64 + j] = v.x;
            spc[(hq * 4 + 1) * 64 + j] = v.y;
            spc[(hq * 4 + 2) * 64 + j] = v.z;
            spc[(hq * 4 + 3) * 64 + j] = v.w;
        }
        if (tid < 128) sw2[tid] = W2[hh * 128 + tid];
        __syncthreads();

#pragma unroll 2
        for (int h = 0; h < 128; h++) {
            float2 a = *(const float2*)&spr[h * 32 + ty * 2];
            float4 c = *(const float4*)&spc[h * 64 + tx * 4];
            float w = sw2[h];
            float av[2] = {a.x, a.y};
            float cv[4] = {c.x, c.y, c.z, c.w};
#pragma unroll
            for (int r = 0; r < 2; r++)
#pragma unroll
                for (int cc = 0; cc < 4; cc++) {
                    float t = av[r] + cv[cc];
                    t = fmaxf(t, 0.f);
                    acc[r][cc] = fmaf(t, w, acc[r][cc]);
                }
        }
    }

    const float bbv = b2[0];
#pragma unroll
    for (int r = 0; r < 2; r++) {
        float4 o;
        o.x = acc[r][0] + bbv;
        o.y = acc[r][1] + bbv;
        o.z = acc[r][2] + bbv;
        o.w = acc[r][3] + bbv;
        *(float4*)&out_edge[b * 65536 + (i0 + ty * 2 + r) * 256 + j0 + tx * 4] = o;
    }
}

// ---------------------------------------------------------------------------
// Kernel 3: per-batch 3-pass radix select (10/11/11 bits) on edge fkeys
//           + per-batch max (pass 0) + S/T sums.  grid 8 x 1024.
// ---------------------------------------------------------------------------
__global__ __launch_bounds__(1024) void select_kernel(const float* __restrict__ edge) {
    __shared__ unsigned int hist[2048];
    __shared__ unsigned int csum[32];
    __shared__ unsigned int s_prefix;
    __shared__ int s_r;
    __shared__ unsigned int redM[32];
    __shared__ float redS[32], redT[32];

    const int b = blockIdx.x, tid = threadIdx.x;
    const int lane = tid & 31;
    const float4* v4 = (const float4*)(edge + b * 65536);

    if (tid == 0) { s_prefix = 0u; s_r = KSEL; }

    unsigned umax = 0u;
#pragma unroll
    for (int pass = 0; pass < 3; pass++) {
        hist[tid] = 0u; hist[tid + 1024] = 0u;
        __syncthreads();
        const unsigned int pref = s_prefix;
        const int shift = (pass == 0) ? 22 : (pass == 1 ? 11 : 0);
        const int hishift = (pass == 1) ? 22 : 11;

        for (int it = tid; it < 16384; it += 1024) {
            float4 q = v4[it];
            float ff[4] = {q.x, q.y, q.z, q.w};
#pragma unroll
            for (int c = 0; c < 4; c++) {
                unsigned int u = fkey(ff[c]);
                if (pass == 0) umax = umax > u ? umax : u;
                bool ok = (pass == 0) || ((u >> hishift) == pref);
                int bin = (int)((u >> shift) & 2047u);
                unsigned int peers = __match_any_sync(0xffffffffu, ok ? bin : -1);
                if (ok && lane == (__ffs(peers) - 1))
                    atomicAdd(&hist[bin], (unsigned)__popc(peers));
            }
        }
        if (pass == 0) {
            unsigned m = umax;
            for (int o = 16; o > 0; o >>= 1)
                m = max(m, __shfl_down_sync(0xffffffffu, m, o));
            if (lane == 0) redM[tid >> 5] = m;
        }
        __syncthreads();

        if (tid < 32) {
            unsigned s = 0;
#pragma unroll 8
            for (int k = 0; k < 64; k++) s += hist[tid * 64 + k];
            csum[tid] = s;
        }
        __syncthreads();
        if (tid == 0) {
            int r = s_r; unsigned cum = 0; int chunk = 0;
            for (int ci = 31; ci >= 0; ci--) {
                if (cum + csum[ci] >= (unsigned)r) { chunk = ci; break; }
                cum += csum[ci];
            }
            int binf = 0;
            for (int k = 63; k >= 0; k--) {
                unsigned c = hist[chunk * 64 + k];
                if (cum + c >= (unsigned)r) { binf = chunk * 64 + k; break; }
                cum += c;
            }
            s_prefix = (pass == 0) ? (unsigned)binf
                                   : ((s_prefix << 11) | (unsigned)binf);
            s_r = r - (int)cum;
            if (pass == 0) {
                unsigned m = 0;
                for (int w = 0; w < 32; w++) m = max(m, redM[w]);
                g_maxkey[b] = m;
            }
        }
        __syncthreads();
    }

    const unsigned thrkey = s_prefix;
    const float M = funkey(g_maxkey[b]);
    float S = 0.f, T = 0.f;
    for (int it = tid; it < 16384; it += 1024) {
        float4 q = v4[it];
        float ff[4] = {q.x, q.y, q.z, q.w};
#pragma unroll
        for (int c = 0; c < 4; c++) {
            float p = expf(2.f * (ff[c] - M));
            S += p;
            if (fkey(ff[c]) >= thrkey) T += p;
        }
    }
    for (int o = 16; o > 0; o >>= 1) {
        S += __shfl_down_sync(0xffffffffu, S, o);
        T += __shfl_down_sync(0xffffffffu, T, o);
    }
    if (lane == 0) { redS[tid >> 5] = S; redT[tid >> 5] = T; }
    __syncthreads();
    if (tid == 0) {
        float s = 0.f, t = 0.f;
#pragma unroll
        for (int w = 0; w < 32; w++) { s += redS[w]; t += redT[w]; }
        g_thrkey[b] = thrkey; g_S[b] = s; g_T[b] = t;
    }
}

// ---------------------------------------------------------------------------
// Kernel 4: finalize — soft, causal, conf from edge in one pass (512 CTAs)
// ---------------------------------------------------------------------------
__global__ __launch_bounds__(256) void finalize_kernel(const float* __restrict__ edge,
                                                       float* __restrict__ causal,
                                                       float* __restrict__ conf,
                                                       float* __restrict__ soft) {
    int i4 = blockIdx.x * 256 + threadIdx.x;
    int b = i4 >> 14;
    const float M = funkey(g_maxkey[b]);
    const unsigned thrkey = g_thrkey[b];
    const float S = g_S[b];
    const float invS = 1.f / S;
    const float invC = 1.f / (g_T[b] + 1e-12f * S);
    float4 e = ((const float4*)edge)[i4];
    float ff[4] = {e.x, e.y, e.z, e.w};
    float4 so, ca, cf;
    float* sop = &so.x; float* cap = &ca.x; float* cfp = &cf.x;
#pragma unroll
    for (int c = 0; c < 4; c++) {
        float p = expf(2.f * (ff[c] - M));
        sop[c] = p * invS;
        float cc = (fkey(ff[c]) >= thrkey) ? p * invC : 0.f;
        cap[c] = cc;
        cfp[c] = 1.f - cc;
    }
    ((float4*)soft)[i4] = so;
    ((float4*)causal)[i4] = ca;
    ((float4*)conf)[i4] = cf;
}

// ---------------------------------------------------------------------------
// Launch — 4 kernels
// ---------------------------------------------------------------------------
extern "C" void kernel_launch(void* const* d_in, const int* in_sizes, int n_in,
                              void* d_out, int out_size) {
    const float* x  = (const float*)d_in[0];
    const float* W1 = (const float*)d_in[1];
    const float* b1 = (const float*)d_in[2];
    const float* W2 = (const float*)d_in[3];
    const float* b2 = (const float*)d_in[4];

    float* out = (float*)d_out;
    float* o_causal = out;
    float* o_conf   = out + QSZ;
    float* o_edge   = out + 2 * QSZ;
    float* o_soft   = out + 3 * QSZ;

    cudaFuncSetAttribute(gemm_mma_kernel,
                         cudaFuncAttributeMaxDynamicSharedMemorySize, GEMM_SMEM);
    cudaFuncSetAttribute(edge_kernel,
                         cudaFuncAttributeMaxDynamicSharedMemorySize, EDGE_SMEM);

    gemm_mma_kernel<<<dim3(8, 32), 256, GEMM_SMEM>>>(x, W1, b1);
    edge_kernel<<<dim3(4, 8, BB), 256, EDGE_SMEM>>>(W2, b2, o_edge);
    select_kernel<<<BB, 1024>>>(o_edge);
    finalize_kernel<<<QSZ / 1024, 256>>>(o_edge, o_causal, o_conf, o_soft);
}